// round 14
// baseline (speedup 1.0000x reference)
#include <cuda_runtime.h>
#include <cstdint>

typedef unsigned long long u64;

#define N_ACT 80
#define M_CON 85
#define NP1   81
#define PDHG_ITERS 200
#define POWER_ITERS 20

// ---- packed f32x2 helpers ----
static __device__ __forceinline__ u64 pk(float lo, float hi) {
    u64 r; asm("mov.b64 %0, {%1, %2};" : "=l"(r) : "f"(lo), "f"(hi)); return r;
}
static __device__ __forceinline__ float2 up(u64 v) {
    float2 f; asm("mov.b64 {%0, %1}, %2;" : "=f"(f.x), "=f"(f.y) : "l"(v)); return f;
}
static __device__ __forceinline__ u64 ff2(u64 a, u64 b, u64 c) {
    u64 r; asm("fma.rn.f32x2 %0, %1, %2, %3;" : "=l"(r) : "l"(a), "l"(b), "l"(c)); return r;
}
static __device__ __forceinline__ u64 add2(u64 a, u64 b) {
    u64 r; asm("add.rn.f32x2 %0, %1, %2;" : "=l"(r) : "l"(a), "l"(b)); return r;
}

__device__ __forceinline__ float warp_sum(float v) {
    #pragma unroll
    for (int off = 16; off > 0; off >>= 1)
        v += __shfl_xor_sync(0xffffffffu, v, off);
    return v;
}
__device__ __forceinline__ float warp_min(float v) {
    #pragma unroll
    for (int off = 16; off > 0; off >>= 1)
        v = fminf(v, __shfl_xor_sync(0xffffffffu, v, off));
    return v;
}

// 44-float packed dot: G[22] (u64 pairs) . V-half (11 ulonglong2 = 44 floats)
__device__ __forceinline__ float dot44(const u64* __restrict__ G,
                                       const ulonglong2* __restrict__ v2) {
    u64 a0 = 0, a1 = 0, a2 = 0, a3 = 0;
    #pragma unroll
    for (int q = 0; q < 10; q += 2) {
        ulonglong2 pa = v2[q];
        ulonglong2 pb = v2[q + 1];
        a0 = ff2(G[2*q + 0], pa.x, a0);
        a1 = ff2(G[2*q + 1], pa.y, a1);
        a2 = ff2(G[2*q + 2], pb.x, a2);
        a3 = ff2(G[2*q + 3], pb.y, a3);
    }
    ulonglong2 pt = v2[10];
    a0 = ff2(G[20], pt.x, a0);
    a1 = ff2(G[21], pt.y, a1);
    u64 s = add2(add2(a0, a1), add2(a2, a3));
    float2 f = up(s);
    return f.x + f.y;
}

// Per-problem shared block; two per CTA.
// Floats: 5*88 + 8 + 85*81 = 7333; pad[3] -> 7336 floats = 29344 B (16B multiple).
struct GSmem {
    float vec[88];   // v / z_bar (0..80); pads zero
    float y[88];     // Gv / y    (0..84)
    float x0[88];    // x0        (0..79)
    float dv[88];    // x_hat-x0  (0..79)
    float d[88];     // row norms (0..84)
    float red[8];
    float As[M_CON * 81];   // pitch 81
    float pad[3];           // round to 16B multiple
};
static_assert(sizeof(GSmem) % 16 == 0, "GSmem must be 16B multiple for LDS.128");

__global__ __launch_bounds__(256, 1)
void acp_kernel(const float* __restrict__ xhat,
                const float* __restrict__ Aglob,
                const float* __restrict__ bglob,
                float* __restrict__ out)
{
    extern __shared__ __align__(16) char smem_raw[];
    GSmem* HA = reinterpret_cast<GSmem*>(smem_raw);
    GSmem* HB = HA + 1;

    const int t    = threadIdx.x;        // 0..255
    const int lane = t & 31;
    const int wid  = t >> 5;             // 0..7
    const int part = lane & 1;           // pair = lanes (2k, 2k+1)
    const int idx  = (lane >> 1) * 8 + wid;   // 0..127, interleaved over warps
    const bool rowAct = (idx < M_CON);
    const bool colAct = (idx < NP1);
    const int pa = blockIdx.x * 2;       // problem A
    const int pb = pa + 1;               // problem B

    // ---- stage both A matrices into shared (coalesced) ----
    {
        const float* ApA = Aglob + (size_t)pa * (M_CON * N_ACT);
        const float* ApB = Aglob + (size_t)pb * (M_CON * N_ACT);
        for (int i = t; i < M_CON * N_ACT; i += 256) {
            int rr = i / N_ACT;
            int cc = i - rr * N_ACT;
            HA->As[rr * 81 + cc] = ApA[i];
            HB->As[rr * 81 + cc] = ApB[i];
        }
    }
    if (t < 88) {
        HA->y[t] = 0.0f;                 HB->y[t] = 0.0f;
        HA->vec[t] = (t < NP1) ? 1.0f : 0.0f;
        HB->vec[t] = (t < NP1) ? 1.0f : 0.0f;
        HA->x0[t] = 0.0f;                HB->x0[t] = 0.0f;
        HA->dv[t] = 0.0f;                HB->dv[t] = 0.0f;
        HA->d[t]  = 0.0f;                HB->d[t]  = 0.0f;
    }
    __syncthreads();

    // ---- per-thread packed halves, both problems ----
    u64 RPa[22], CPa[22], RPb[22], CPb[22];
    float bvalA = 0.0f, bvalB = 0.0f;

    #pragma unroll
    for (int k = 0; k < 22; k++) { RPa[k] = 0; CPa[k] = 0; RPb[k] = 0; CPb[k] = 0; }

    // row fill + norms (shfl hoisted to warp scope)
    {
        float ssA = 0.0f, ssB = 0.0f;
        if (rowAct) {
            const float* ArA = &HA->As[idx * 81];
            const float* ArB = &HB->As[idx * 81];
            if (part == 0) {
                #pragma unroll
                for (int k = 0; k < 22; k++) {
                    float la = ArA[2*k], ha = ArA[2*k + 1];
                    float lb = ArB[2*k], hb = ArB[2*k + 1];
                    RPa[k] = pk(la, ha);  ssA = fmaf(la, la, fmaf(ha, ha, ssA));
                    RPb[k] = pk(lb, hb);  ssB = fmaf(lb, lb, fmaf(hb, hb, ssB));
                }
            } else {
                #pragma unroll
                for (int k = 0; k < 18; k++) {
                    float la = ArA[44 + 2*k], ha = ArA[45 + 2*k];
                    float lb = ArB[44 + 2*k], hb = ArB[45 + 2*k];
                    RPa[k] = pk(la, ha);  ssA = fmaf(la, la, fmaf(ha, ha, ssA));
                    RPb[k] = pk(lb, hb);  ssB = fmaf(lb, lb, fmaf(hb, hb, ssB));
                }
            }
        }
        float totA = ssA + __shfl_xor_sync(0xffffffffu, ssA, 1);
        float totB = ssB + __shfl_xor_sync(0xffffffffu, ssB, 1);
        if (rowAct) {
            float dA = fmaxf(sqrtf(totA), 1e-12f);
            float dB = fmaxf(sqrtf(totB), 1e-12f);
            if (part == 1) { RPa[18] = pk(dA, 0.0f); RPb[18] = pk(dB, 0.0f); }
            if (part == 0) { HA->d[idx] = dA; HB->d[idx] = dB; }
            bvalA = bglob[(size_t)pa * M_CON + idx];
            bvalB = bglob[(size_t)pb * M_CON + idx];
        }
    }
    __syncthreads();                     // d complete (pads still zero)

    // col fill
    if (colAct) {
        if (idx < N_ACT) {
            if (part == 0) {
                #pragma unroll
                for (int k = 0; k < 22; k++) {
                    CPa[k] = pk(HA->As[(2*k) * 81 + idx], HA->As[(2*k + 1) * 81 + idx]);
                    CPb[k] = pk(HB->As[(2*k) * 81 + idx], HB->As[(2*k + 1) * 81 + idx]);
                }
            } else {
                #pragma unroll
                for (int k = 0; k < 20; k++) {
                    CPa[k] = pk(HA->As[(44 + 2*k) * 81 + idx], HA->As[(45 + 2*k) * 81 + idx]);
                    CPb[k] = pk(HB->As[(44 + 2*k) * 81 + idx], HB->As[(45 + 2*k) * 81 + idx]);
                }
                CPa[20] = pk(HA->As[84 * 81 + idx], 0.0f);
                CPb[20] = pk(HB->As[84 * 81 + idx], 0.0f);
            }
        } else {   // idx == 80: column is d (zero-padded to 88)
            #pragma unroll
            for (int k = 0; k < 22; k++) {
                CPa[k] = pk(HA->d[44 * part + 2*k], HA->d[44 * part + 2*k + 1]);
                CPb[k] = pk(HB->d[44 * part + 2*k], HB->d[44 * part + 2*k + 1]);
            }
        }
    }

    const ulonglong2* vecA = reinterpret_cast<const ulonglong2*>(HA->vec) + 11 * part;
    const ulonglong2* yA   = reinterpret_cast<const ulonglong2*>(HA->y)   + 11 * part;
    const ulonglong2* vecB = reinterpret_cast<const ulonglong2*>(HB->vec) + 11 * part;
    const ulonglong2* yB   = reinterpret_cast<const ulonglong2*>(HB->y)   + 11 * part;

    // ---- power iteration (both problems), normalize every 3rd iter + last ----
    for (int pi = 0; pi < POWER_ITERS; pi++) {
        float prA = dot44(RPa, vecA);
        float prB = dot44(RPb, vecB);
        float gA = prA + __shfl_xor_sync(0xffffffffu, prA, 1);
        float gB = prB + __shfl_xor_sync(0xffffffffu, prB, 1);
        if (rowAct && part == 0) { HA->y[idx] = gA; HB->y[idx] = gB; }
        __syncthreads();
        float pcA = dot44(CPa, yA);
        float pcB = dot44(CPb, yB);
        float wA = pcA + __shfl_xor_sync(0xffffffffu, pcA, 1);
        float wB = pcB + __shfl_xor_sync(0xffffffffu, pcB, 1);
        const bool norm_now = ((pi % 3) == 2) || (pi == POWER_ITERS - 1);
        if (norm_now) {
            bool act = (colAct && part == 0);
            float sA = warp_sum(act ? wA * wA : 0.0f);
            float sB = warp_sum(act ? wB * wB : 0.0f);
            if (lane == 0) { HA->red[wid] = sA; HB->red[wid] = sB; }
            __syncthreads();
            float nA = sqrtf(((HA->red[0] + HA->red[1]) + (HA->red[2] + HA->red[3])) +
                             ((HA->red[4] + HA->red[5]) + (HA->red[6] + HA->red[7]))) + 1e-12f;
            float nB = sqrtf(((HB->red[0] + HB->red[1]) + (HB->red[2] + HB->red[3])) +
                             ((HB->red[4] + HB->red[5]) + (HB->red[6] + HB->red[7]))) + 1e-12f;
            if (act) { HA->vec[idx] = wA / nA; HB->vec[idx] = wB / nB; }
        } else {
            if (colAct && part == 0) { HA->vec[idx] = wA; HB->vec[idx] = wB; }
        }
        __syncthreads();
    }
    // L = ||G v|| for both
    float tauA, tauB;
    {
        float prA = dot44(RPa, vecA);
        float prB = dot44(RPb, vecB);
        float gA = prA + __shfl_xor_sync(0xffffffffu, prA, 1);
        float gB = prB + __shfl_xor_sync(0xffffffffu, prB, 1);
        bool act = (rowAct && part == 0);
        float sA = warp_sum(act ? gA * gA : 0.0f);
        float sB = warp_sum(act ? gB * gB : 0.0f);
        if (lane == 0) { HA->red[wid] = sA; HB->red[wid] = sB; }
        __syncthreads();
        float LA = sqrtf(((HA->red[0] + HA->red[1]) + (HA->red[2] + HA->red[3])) +
                         ((HA->red[4] + HA->red[5]) + (HA->red[6] + HA->red[7])));
        float LB = sqrtf(((HB->red[0] + HB->red[1]) + (HB->red[2] + HB->red[3])) +
                         ((HB->red[4] + HB->red[5]) + (HB->red[6] + HB->red[7])));
        tauA = 0.9f / fmaxf(LA, 1e-6f);
        tauB = 0.9f / fmaxf(LB, 1e-6f);
    }

    // ---- PDHG: 200 fixed iterations, both problems ----
    if (t < 88) { HA->y[t] = 0.0f; HB->y[t] = 0.0f; }
    float zvA = 0.0f, yvA = 0.0f, zvB = 0.0f, yvB = 0.0f;
    const float cterm = (idx == N_ACT) ? -1.0f : 0.0f;
    __syncthreads();

    for (int it = 0; it < PDHG_ITERS; it++) {
        float pcA = dot44(CPa, yA);
        float pcB = dot44(CPb, yB);
        float gtyA = pcA + __shfl_xor_sync(0xffffffffu, pcA, 1);
        float gtyB = pcB + __shfl_xor_sync(0xffffffffu, pcB, 1);
        float znA = fmaxf(zvA - tauA * (cterm + gtyA), 0.0f);
        float znB = fmaxf(zvB - tauB * (cterm + gtyB), 0.0f);
        if (colAct && part == 0) {
            HA->vec[idx] = 2.0f * znA - zvA;
            HB->vec[idx] = 2.0f * znB - zvB;
        }
        zvA = znA; zvB = znB;
        __syncthreads();
        float prA = dot44(RPa, vecA);
        float prB = dot44(RPb, vecB);
        float gzA = prA + __shfl_xor_sync(0xffffffffu, prA, 1);
        float gzB = prB + __shfl_xor_sync(0xffffffffu, prB, 1);
        yvA = fmaxf(yvA + tauA * (gzA - bvalA), 0.0f);
        yvB = fmaxf(yvB + tauB * (gzB - bvalB), 0.0f);
        if (rowAct && part == 0) { HA->y[idx] = yvA; HB->y[idx] = yvB; }
        __syncthreads();
    }

    // ---- alpha map, both problems ----
    if (idx < N_ACT && part == 0) {
        HA->x0[idx] = zvA;
        HA->dv[idx] = xhat[(size_t)pa * N_ACT + idx] - zvA;
        HB->x0[idx] = zvB;
        HB->dv[idx] = xhat[(size_t)pb * N_ACT + idx] - zvB;
    }
    __syncthreads();

    const float INF = __int_as_float(0x7f800000);
    float aiA, aiB;
    {
        const ulonglong2* x0A = reinterpret_cast<const ulonglong2*>(HA->x0) + 11 * part;
        const ulonglong2* dvA = reinterpret_cast<const ulonglong2*>(HA->dv) + 11 * part;
        const ulonglong2* x0B = reinterpret_cast<const ulonglong2*>(HB->x0) + 11 * part;
        const ulonglong2* dvB = reinterpret_cast<const ulonglong2*>(HB->dv) + 11 * part;
        float p0A = dot44(RPa, x0A);
        float p1A = dot44(RPa, dvA);
        float p0B = dot44(RPb, x0B);
        float p1B = dot44(RPb, dvB);
        float ax0A = p0A + __shfl_xor_sync(0xffffffffu, p0A, 1);
        float adA  = p1A + __shfl_xor_sync(0xffffffffu, p1A, 1);
        float ax0B = p0B + __shfl_xor_sync(0xffffffffu, p0B, 1);
        float adB  = p1B + __shfl_xor_sync(0xffffffffu, p1B, 1);
        if (rowAct) {
            float slA = fmaxf(bvalA - ax0A, 0.0f);
            float slB = fmaxf(bvalB - ax0B, 0.0f);
            aiA = (adA > 0.0f) ? (slA / (adA + 1e-12f)) : INF;
            aiB = (adB > 0.0f) ? (slB / (adB + 1e-12f)) : INF;
        } else {
            aiA = INF; aiB = INF;
        }
    }
    aiA = warp_min(aiA);
    aiB = warp_min(aiB);
    if (lane == 0) { HA->red[wid] = aiA; HB->red[wid] = aiB; }
    __syncthreads();
    float alA = fminf(fminf(fminf(HA->red[0], HA->red[1]), fminf(HA->red[2], HA->red[3])),
                      fminf(fminf(HA->red[4], HA->red[5]), fminf(HA->red[6], HA->red[7])));
    float alB = fminf(fminf(fminf(HB->red[0], HB->red[1]), fminf(HB->red[2], HB->red[3])),
                      fminf(fminf(HB->red[4], HB->red[5]), fminf(HB->red[6], HB->red[7])));
    if (!isfinite(alA)) alA = 1.0f;
    if (!isfinite(alB)) alB = 1.0f;
    alA = fminf(fmaxf(alA - 1e-9f, 0.0f), 1.0f);
    alB = fminf(fmaxf(alB - 1e-9f, 0.0f), 1.0f);

    if (idx < N_ACT && part == 0) {
        out[(size_t)pa * N_ACT + idx] = fmaxf(HA->x0[idx] + alA * HA->dv[idx], 0.0f);
        out[(size_t)pb * N_ACT + idx] = fmaxf(HB->x0[idx] + alB * HB->dv[idx], 0.0f);
    }
}

extern "C" void kernel_launch(void* const* d_in, const int* in_sizes, int n_in,
                              void* d_out, int out_size)
{
    const float* xhat = (const float*)d_in[0];
    const float* A    = (const float*)d_in[1];
    const float* b    = (const float*)d_in[2];
    float* out        = (float*)d_out;
    int P = in_sizes[0] / N_ACT;            // 1024 problems (even)

    size_t smem = 2 * sizeof(GSmem);        // two problems per CTA (~58.7 KB)
    cudaFuncSetAttribute(acp_kernel,
                         cudaFuncAttributeMaxDynamicSharedMemorySize,
                         (int)smem);

    int grid = P / 2;                       // 512
    acp_kernel<<<grid, 256, smem>>>(xhat, A, b, out);
}